// round 1
// baseline (speedup 1.0000x reference)
#include <cuda_runtime.h>
#include <cuda_bf16.h>

// TriPlane bilinear sampling, GB300.
// Strategy:
//  1) transpose_kernel: [C=64, H=256, W=256] f32 -> scratch [H, W, C] f32
//     (channels contiguous per texel -> coalesced gathers)
//  2) sample_kernel: warp per point; lane handles 2 channels (float2).
//     12 corner loads per point, each a single 256B coalesced transaction.

#define NPTS   1048576
#define RES    256
#define FEAT   64
#define PLANE_ELEMS (RES * RES * FEAT)   // 4,194,304 floats = 16 MB

// 48 MB transposed plane scratch (static device array: allocation-free)
__device__ float g_tp[3 * PLANE_ELEMS];

// ---------------------------------------------------------------------------
// Transpose [64,256,256] -> [256,256,64] with smem tile (conflict-free)
// grid: (RES/32 x-tiles = 8, FEAT/32 c-tiles = 2, RES rows = 256)
// block: (32, 32)
// ---------------------------------------------------------------------------
__global__ void transpose_kernel(const float* __restrict__ src, int plane_idx) {
    __shared__ float tile[32][33];
    const int y  = blockIdx.z;
    const int x0 = blockIdx.x * 32;
    const int c0 = blockIdx.y * 32;
    const int tx = threadIdx.x;
    const int ty = threadIdx.y;

    // read src[c0+ty][y][x0+tx]  (coalesced in tx)
    tile[ty][tx] = src[(c0 + ty) * (RES * RES) + y * RES + (x0 + tx)];
    __syncthreads();

    // write dst[(y*RES + x0+ty)*FEAT + c0+tx]  (coalesced in tx)
    float* dst = g_tp + plane_idx * PLANE_ELEMS;
    dst[(y * RES + (x0 + ty)) * FEAT + (c0 + tx)] = tile[tx][ty];
}

// ---------------------------------------------------------------------------
// Sampler: one warp per point, lane owns channels {2*lane, 2*lane+1}
// ---------------------------------------------------------------------------
__device__ __forceinline__ void sample_plane(const float* __restrict__ plane,
                                             float u, float v, int lane,
                                             float2& acc) {
    float ix = (u + 1.0f) * 0.5f * (float)(RES - 1);
    float iy = (v + 1.0f) * 0.5f * (float)(RES - 1);
    float fx0 = floorf(ix);
    float fy0 = floorf(iy);

    // weights from unclamped floor coords (matches reference)
    float wx1 = ix - fx0;
    float wx0 = (fx0 + 1.0f) - ix;
    float wy1 = iy - fy0;
    float wy0 = (fy0 + 1.0f) - iy;

    int x0 = (int)fx0;
    int x1 = x0 + 1;
    int y0 = (int)fy0;
    int y1 = y0 + 1;
    x0 = max(0, min(RES - 1, x0));
    x1 = max(0, min(RES - 1, x1));
    y0 = max(0, min(RES - 1, y0));
    y1 = max(0, min(RES - 1, y1));

    const float2* r0c0 = (const float2*)(plane + (y0 * RES + x0) * FEAT) + lane;
    const float2* r0c1 = (const float2*)(plane + (y0 * RES + x1) * FEAT) + lane;
    const float2* r1c0 = (const float2*)(plane + (y1 * RES + x0) * FEAT) + lane;
    const float2* r1c1 = (const float2*)(plane + (y1 * RES + x1) * FEAT) + lane;

    float2 v00 = __ldg(r0c0);
    float2 v01 = __ldg(r0c1);
    float2 v10 = __ldg(r1c0);
    float2 v11 = __ldg(r1c1);

    float w00 = wx0 * wy0;
    float w01 = wx1 * wy0;
    float w10 = wx0 * wy1;
    float w11 = wx1 * wy1;

    acc.x += w00 * v00.x + w01 * v01.x + w10 * v10.x + w11 * v11.x;
    acc.y += w00 * v00.y + w01 * v01.y + w10 * v10.y + w11 * v11.y;
}

__global__ __launch_bounds__(256) void sample_kernel(const float* __restrict__ x,
                                                     float* __restrict__ out) {
    const int gtid = blockIdx.x * blockDim.x + threadIdx.x;
    const int p    = gtid >> 5;      // point index (warp id)
    const int lane = gtid & 31;
    if (p >= NPTS) return;

    const float px = __ldg(x + 3 * p + 0);
    const float py = __ldg(x + 3 * p + 1);
    const float pz = __ldg(x + 3 * p + 2);

    float2 acc = make_float2(0.0f, 0.0f);
    sample_plane(g_tp + 0 * PLANE_ELEMS, px, py, lane, acc);   // xy plane
    sample_plane(g_tp + 1 * PLANE_ELEMS, px, pz, lane, acc);   // xz plane
    sample_plane(g_tp + 2 * PLANE_ELEMS, py, pz, lane, acc);   // yz plane

    const float inv3 = 1.0f / 3.0f;
    float2 r = make_float2(acc.x * inv3, acc.y * inv3);
    ((float2*)out)[p * 32 + lane] = r;
}

// ---------------------------------------------------------------------------
extern "C" void kernel_launch(void* const* d_in, const int* in_sizes, int n_in,
                              void* d_out, int out_size) {
    const float* x        = (const float*)d_in[0];
    const float* plane_xy = (const float*)d_in[1];
    const float* plane_xz = (const float*)d_in[2];
    const float* plane_yz = (const float*)d_in[3];
    float* out = (float*)d_out;

    dim3 tblock(32, 32);
    dim3 tgrid(RES / 32, FEAT / 32, RES);
    transpose_kernel<<<tgrid, tblock>>>(plane_xy, 0);
    transpose_kernel<<<tgrid, tblock>>>(plane_xz, 1);
    transpose_kernel<<<tgrid, tblock>>>(plane_yz, 2);

    // warp per point: NPTS warps = NPTS*32 threads, 256 threads/block
    const int threads = 256;
    const int blocks  = (NPTS * 32) / threads;   // 131072
    sample_kernel<<<blocks, threads>>>(x, out);
}

// round 2
// speedup vs baseline: 1.8688x; 1.8688x over previous
#include <cuda_runtime.h>
#include <cuda_fp16.h>

// TriPlane bilinear sampling, GB300 — round 2.
//  1) Fused transpose+convert: [C=64,H=256,W=256] f32 -> [H,W,C] fp16 (one kernel, 3 planes)
//  2) Sampler: 8 lanes per point (4 points/warp); each lane owns 8 channels,
//     one LDG.128 per corner. fp32 weights + fp32 accumulation.

#define NPTS   1048576
#define RES    256
#define FEAT   64
#define PLANE_ELEMS (RES * RES * FEAT)   // 4,194,304

// 24 MB fp16 transposed plane scratch
__device__ __half g_tp16[3 * PLANE_ELEMS];

// ---------------------------------------------------------------------------
// Transpose + f32->fp16 convert.
// grid: (RES/32 = 8 x-tiles, RES = 256 rows y, 3 planes), block = 256
// ---------------------------------------------------------------------------
__global__ __launch_bounds__(256) void transpose_kernel(
    const float* __restrict__ p0,
    const float* __restrict__ p1,
    const float* __restrict__ p2)
{
    __shared__ float tile[FEAT][33];   // 64 x 33 floats = 8.4 KB
    const int x0    = blockIdx.x * 32;
    const int y     = blockIdx.y;
    const int plane = blockIdx.z;
    const int tid   = threadIdx.x;

    const float* src = (plane == 0) ? p0 : (plane == 1) ? p1 : p2;

    // load 64 channels x 32 x-positions (coalesced along x)
    #pragma unroll
    for (int i = 0; i < 8; i++) {
        int idx = tid + i * 256;
        int c  = idx >> 5;
        int xx = idx & 31;
        tile[c][xx] = src[c * (RES * RES) + y * RES + (x0 + xx)];
    }
    __syncthreads();

    // write fp16: texel (y, x0+xx), channel-pair cp -> half2 (coalesced along cp)
    __half* dst = g_tp16 + plane * PLANE_ELEMS;
    #pragma unroll
    for (int i = 0; i < 4; i++) {
        int idx = tid + i * 256;
        int xx = idx >> 5;
        int cp = idx & 31;
        float2 f = make_float2(tile[2 * cp][xx], tile[2 * cp + 1][xx]);
        ((half2*)(dst + ((y * RES + (x0 + xx)) * FEAT)))[cp] = __float22half2_rn(f);
    }
}

// ---------------------------------------------------------------------------
// Sampler: 8 lanes/point. Lane `sub` owns channels [8*sub, 8*sub+8).
// ---------------------------------------------------------------------------
__device__ __forceinline__ void sample_plane(const __half* __restrict__ plane,
                                             float u, float v, int sub,
                                             float acc[8]) {
    float ix = (u + 1.0f) * 0.5f * (float)(RES - 1);
    float iy = (v + 1.0f) * 0.5f * (float)(RES - 1);
    float fx0 = floorf(ix);
    float fy0 = floorf(iy);

    float wx1 = ix - fx0;
    float wx0 = (fx0 + 1.0f) - ix;
    float wy1 = iy - fy0;
    float wy0 = (fy0 + 1.0f) - iy;

    int x0 = (int)fx0;
    int x1 = min(RES - 1, x0 + 1);
    int y0 = (int)fy0;
    int y1 = min(RES - 1, y0 + 1);
    x0 = max(0, min(RES - 1, x0));
    y0 = max(0, min(RES - 1, y0));
    x1 = max(0, x1);
    y1 = max(0, y1);

    const uint4* t00 = (const uint4*)(plane + (y0 * RES + x0) * FEAT) + sub;
    const uint4* t01 = (const uint4*)(plane + (y0 * RES + x1) * FEAT) + sub;
    const uint4* t10 = (const uint4*)(plane + (y1 * RES + x0) * FEAT) + sub;
    const uint4* t11 = (const uint4*)(plane + (y1 * RES + x1) * FEAT) + sub;

    uint4 r00 = __ldg(t00);
    uint4 r01 = __ldg(t01);
    uint4 r10 = __ldg(t10);
    uint4 r11 = __ldg(t11);

    float w00 = wx0 * wy0;
    float w01 = wx1 * wy0;
    float w10 = wx0 * wy1;
    float w11 = wx1 * wy1;

    const half2* h00 = (const half2*)&r00;
    const half2* h01 = (const half2*)&r01;
    const half2* h10 = (const half2*)&r10;
    const half2* h11 = (const half2*)&r11;

    #pragma unroll
    for (int j = 0; j < 4; j++) {
        float2 f00 = __half22float2(h00[j]);
        float2 f01 = __half22float2(h01[j]);
        float2 f10 = __half22float2(h10[j]);
        float2 f11 = __half22float2(h11[j]);
        acc[2 * j]     += w00 * f00.x + w01 * f01.x + w10 * f10.x + w11 * f11.x;
        acc[2 * j + 1] += w00 * f00.y + w01 * f01.y + w10 * f10.y + w11 * f11.y;
    }
}

__global__ __launch_bounds__(256) void sample_kernel(const float* __restrict__ x,
                                                     float* __restrict__ out) {
    const int gtid = blockIdx.x * blockDim.x + threadIdx.x;
    const int p    = gtid >> 3;       // point index (8 lanes/point)
    const int sub  = gtid & 7;

    const float px = __ldg(x + 3 * p + 0);
    const float py = __ldg(x + 3 * p + 1);
    const float pz = __ldg(x + 3 * p + 2);

    float acc[8];
    #pragma unroll
    for (int i = 0; i < 8; i++) acc[i] = 0.0f;

    sample_plane(g_tp16 + 0 * PLANE_ELEMS, px, py, sub, acc);
    sample_plane(g_tp16 + 1 * PLANE_ELEMS, px, pz, sub, acc);
    sample_plane(g_tp16 + 2 * PLANE_ELEMS, py, pz, sub, acc);

    const float inv3 = 1.0f / 3.0f;
    float4 o0 = make_float4(acc[0] * inv3, acc[1] * inv3, acc[2] * inv3, acc[3] * inv3);
    float4 o1 = make_float4(acc[4] * inv3, acc[5] * inv3, acc[6] * inv3, acc[7] * inv3);
    float4* dst = (float4*)(out + p * FEAT) + sub * 2;
    dst[0] = o0;
    dst[1] = o1;
}

// ---------------------------------------------------------------------------
extern "C" void kernel_launch(void* const* d_in, const int* in_sizes, int n_in,
                              void* d_out, int out_size) {
    const float* x        = (const float*)d_in[0];
    const float* plane_xy = (const float*)d_in[1];
    const float* plane_xz = (const float*)d_in[2];
    const float* plane_yz = (const float*)d_in[3];
    float* out = (float*)d_out;

    dim3 tgrid(RES / 32, RES, 3);
    transpose_kernel<<<tgrid, 256>>>(plane_xy, plane_xz, plane_yz);

    // 8 lanes per point -> NPTS*8 threads
    const int threads = 256;
    const int blocks  = (NPTS * 8) / threads;   // 32768
    sample_kernel<<<blocks, threads>>>(x, out);
}

// round 3
// speedup vs baseline: 2.1594x; 1.1555x over previous
#include <cuda_runtime.h>
#include <cuda_fp16.h>

// TriPlane bilinear sampling, GB300 — round 3.
//  1) Fused transpose+convert: [C=64,H=256,W=256] f32 -> [H,W,C] fp16
//  2) Sampler: 8 lanes/point (4 points/warp), lane owns 8 channels,
//     one LDG.128 per corner, HFMA2 accumulation (no per-texel cvt).

#define NPTS   1048576
#define RES    256
#define FEAT   64
#define PLANE_ELEMS (RES * RES * FEAT)   // 4,194,304

// 24 MB fp16 transposed plane scratch
__device__ __half g_tp16[3 * PLANE_ELEMS];

// ---------------------------------------------------------------------------
// Transpose + f32->fp16 convert.
// grid: (RES/32 = 8 x-tiles, RES = 256 rows y, 3 planes), block = 256
// ---------------------------------------------------------------------------
__global__ __launch_bounds__(256) void transpose_kernel(
    const float* __restrict__ p0,
    const float* __restrict__ p1,
    const float* __restrict__ p2)
{
    __shared__ float tile[FEAT][33];
    const int x0    = blockIdx.x * 32;
    const int y     = blockIdx.y;
    const int plane = blockIdx.z;
    const int tid   = threadIdx.x;

    const float* src = (plane == 0) ? p0 : (plane == 1) ? p1 : p2;

    #pragma unroll
    for (int i = 0; i < 8; i++) {
        int idx = tid + i * 256;
        int c  = idx >> 5;
        int xx = idx & 31;
        tile[c][xx] = src[c * (RES * RES) + y * RES + (x0 + xx)];
    }
    __syncthreads();

    __half* dst = g_tp16 + plane * PLANE_ELEMS;
    #pragma unroll
    for (int i = 0; i < 4; i++) {
        int idx = tid + i * 256;
        int xx = idx >> 5;
        int cp = idx & 31;
        float2 f = make_float2(tile[2 * cp][xx], tile[2 * cp + 1][xx]);
        ((half2*)(dst + ((y * RES + (x0 + xx)) * FEAT)))[cp] = __float22half2_rn(f);
    }
}

// ---------------------------------------------------------------------------
// Sampler: 8 lanes/point. Lane `sub` owns channels [8*sub, 8*sub+8).
// acc: 4 x half2 (8 channels), accumulated across all 3 planes with HFMA2.
// ---------------------------------------------------------------------------
__device__ __forceinline__ void sample_plane_h(const uint4* __restrict__ pbase,
                                               float u, float v,
                                               half2 acc[4]) {
    float ix = (u + 1.0f) * 0.5f * (float)(RES - 1);
    float iy = (v + 1.0f) * 0.5f * (float)(RES - 1);
    float fx0 = floorf(ix);
    float fy0 = floorf(iy);

    float wx1 = ix - fx0;
    float wx0 = (fx0 + 1.0f) - ix;
    float wy1 = iy - fy0;
    float wy0 = (fy0 + 1.0f) - iy;

    // x in [-1, 1): only upper clamp on the +1 neighbors can trigger
    int x0 = (int)fx0;
    int y0 = (int)fy0;
    int x1 = min(RES - 1, x0 + 1);
    int y1 = min(RES - 1, y0 + 1);

    // uint4 index: (y*256 + x)*8  (8 uint4 = 64 halves per texel)
    int ry0 = y0 << 11;
    int ry1 = y1 << 11;
    int cx0 = x0 << 3;
    int cx1 = x1 << 3;

    uint4 r00 = __ldg(pbase + (ry0 + cx0));
    uint4 r01 = __ldg(pbase + (ry0 + cx1));
    uint4 r10 = __ldg(pbase + (ry1 + cx0));
    uint4 r11 = __ldg(pbase + (ry1 + cx1));

    half2 w00 = __float2half2_rn(wx0 * wy0);
    half2 w01 = __float2half2_rn(wx1 * wy0);
    half2 w10 = __float2half2_rn(wx0 * wy1);
    half2 w11 = __float2half2_rn(wx1 * wy1);

    const half2* h00 = (const half2*)&r00;
    const half2* h01 = (const half2*)&r01;
    const half2* h10 = (const half2*)&r10;
    const half2* h11 = (const half2*)&r11;

    #pragma unroll
    for (int j = 0; j < 4; j++) {
        half2 a = acc[j];
        a = __hfma2(w00, h00[j], a);
        a = __hfma2(w01, h01[j], a);
        a = __hfma2(w10, h10[j], a);
        a = __hfma2(w11, h11[j], a);
        acc[j] = a;
    }
}

__global__ __launch_bounds__(256) void sample_kernel(const float* __restrict__ x,
                                                     float* __restrict__ out) {
    const int gtid = blockIdx.x * blockDim.x + threadIdx.x;
    const int p    = gtid >> 3;       // point index (8 lanes/point)
    const int sub  = gtid & 7;

    const float px = __ldg(x + 3 * p + 0);
    const float py = __ldg(x + 3 * p + 1);
    const float pz = __ldg(x + 3 * p + 2);

    half2 acc[4];
    #pragma unroll
    for (int i = 0; i < 4; i++) acc[i] = __float2half2_rn(0.0f);

    const uint4* base0 = (const uint4*)(g_tp16 + 0 * PLANE_ELEMS) + sub;
    const uint4* base1 = (const uint4*)(g_tp16 + 1 * PLANE_ELEMS) + sub;
    const uint4* base2 = (const uint4*)(g_tp16 + 2 * PLANE_ELEMS) + sub;

    sample_plane_h(base0, px, py, acc);
    sample_plane_h(base1, px, pz, acc);
    sample_plane_h(base2, py, pz, acc);

    const float inv3 = 1.0f / 3.0f;
    float2 f0 = __half22float2(acc[0]);
    float2 f1 = __half22float2(acc[1]);
    float2 f2 = __half22float2(acc[2]);
    float2 f3 = __half22float2(acc[3]);
    float4 o0 = make_float4(f0.x * inv3, f0.y * inv3, f1.x * inv3, f1.y * inv3);
    float4 o1 = make_float4(f2.x * inv3, f2.y * inv3, f3.x * inv3, f3.y * inv3);
    float4* dst = (float4*)(out + p * FEAT) + sub * 2;
    dst[0] = o0;
    dst[1] = o1;
}

// ---------------------------------------------------------------------------
extern "C" void kernel_launch(void* const* d_in, const int* in_sizes, int n_in,
                              void* d_out, int out_size) {
    const float* x        = (const float*)d_in[0];
    const float* plane_xy = (const float*)d_in[1];
    const float* plane_xz = (const float*)d_in[2];
    const float* plane_yz = (const float*)d_in[3];
    float* out = (float*)d_out;

    dim3 tgrid(RES / 32, RES, 3);
    transpose_kernel<<<tgrid, 256>>>(plane_xy, plane_xz, plane_yz);

    const int threads = 256;
    const int blocks  = (NPTS * 8) / threads;   // 32768
    sample_kernel<<<blocks, threads>>>(x, out);
}

// round 4
// speedup vs baseline: 2.2086x; 1.0228x over previous
#include <cuda_runtime.h>
#include <cuda_fp16.h>

// TriPlane bilinear sampling, GB300 — round 4.
//  1) Fused transpose+convert: [C=64,H=256,W=256] f32 -> [H,W,C] fp16
//  2) Sampler: 8 lanes/point; ALL 12 corner LDG.128 issued upfront (MLP=12)
//     to hide L2 latency; half2 per-plane FMA, fp32 cross-plane accumulation.

#define NPTS   1048576
#define RES    256
#define FEAT   64
#define PLANE_ELEMS (RES * RES * FEAT)

__device__ __half g_tp16[3 * PLANE_ELEMS];

// ---------------------------------------------------------------------------
__global__ __launch_bounds__(256) void transpose_kernel(
    const float* __restrict__ p0,
    const float* __restrict__ p1,
    const float* __restrict__ p2)
{
    __shared__ float tile[FEAT][33];
    const int x0    = blockIdx.x * 32;
    const int y     = blockIdx.y;
    const int plane = blockIdx.z;
    const int tid   = threadIdx.x;

    const float* src = (plane == 0) ? p0 : (plane == 1) ? p1 : p2;

    #pragma unroll
    for (int i = 0; i < 8; i++) {
        int idx = tid + i * 256;
        int c  = idx >> 5;
        int xx = idx & 31;
        tile[c][xx] = src[c * (RES * RES) + y * RES + (x0 + xx)];
    }
    __syncthreads();

    __half* dst = g_tp16 + plane * PLANE_ELEMS;
    #pragma unroll
    for (int i = 0; i < 4; i++) {
        int idx = tid + i * 256;
        int xx = idx >> 5;
        int cp = idx & 31;
        float2 f = make_float2(tile[2 * cp][xx], tile[2 * cp + 1][xx]);
        ((half2*)(dst + ((y * RES + (x0 + xx)) * FEAT)))[cp] = __float22half2_rn(f);
    }
}

// ---------------------------------------------------------------------------
// Address + weight computation for one plane.
__device__ __forceinline__ void plane_setup(float u, float v,
                                            int& i00, int& i01, int& i10, int& i11,
                                            half2 w[4]) {
    float ix = (u + 1.0f) * 0.5f * (float)(RES - 1);
    float iy = (v + 1.0f) * 0.5f * (float)(RES - 1);
    float fx0 = floorf(ix);
    float fy0 = floorf(iy);

    float wx1 = ix - fx0;
    float wx0 = (fx0 + 1.0f) - ix;
    float wy1 = iy - fy0;
    float wy0 = (fy0 + 1.0f) - iy;

    int x0 = (int)fx0;
    int y0 = (int)fy0;
    int x1 = min(RES - 1, x0 + 1);
    int y1 = min(RES - 1, y0 + 1);

    int ry0 = y0 << 11, ry1 = y1 << 11;   // uint4 units: (y*256 + x)*8
    int cx0 = x0 << 3,  cx1 = x1 << 3;
    i00 = ry0 + cx0;  i01 = ry0 + cx1;
    i10 = ry1 + cx0;  i11 = ry1 + cx1;

    w[0] = __float2half2_rn(wx0 * wy0);
    w[1] = __float2half2_rn(wx1 * wy0);
    w[2] = __float2half2_rn(wx0 * wy1);
    w[3] = __float2half2_rn(wx1 * wy1);
}

// Consume 4 corner texel regs for one plane -> add into fp32 acc[8].
__device__ __forceinline__ void plane_reduce(const uint4& r00, const uint4& r01,
                                             const uint4& r10, const uint4& r11,
                                             const half2 w[4], float acc[8]) {
    const half2* h00 = (const half2*)&r00;
    const half2* h01 = (const half2*)&r01;
    const half2* h10 = (const half2*)&r10;
    const half2* h11 = (const half2*)&r11;
    #pragma unroll
    for (int j = 0; j < 4; j++) {
        half2 a = __hmul2(w[0], h00[j]);
        a = __hfma2(w[1], h01[j], a);
        a = __hfma2(w[2], h10[j], a);
        a = __hfma2(w[3], h11[j], a);
        float2 f = __half22float2(a);
        acc[2 * j]     += f.x;
        acc[2 * j + 1] += f.y;
    }
}

__global__ __launch_bounds__(256) void sample_kernel(const float* __restrict__ x,
                                                     float* __restrict__ out) {
    const int gtid = blockIdx.x * blockDim.x + threadIdx.x;
    const int p    = gtid >> 3;
    const int sub  = gtid & 7;

    const float px = __ldg(x + 3 * p + 0);
    const float py = __ldg(x + 3 * p + 1);
    const float pz = __ldg(x + 3 * p + 2);

    int a00, a01, a10, a11;
    int b00, b01, b10, b11;
    int c00, c01, c10, c11;
    half2 wa[4], wb[4], wc[4];
    plane_setup(px, py, a00, a01, a10, a11, wa);
    plane_setup(px, pz, b00, b01, b10, b11, wb);
    plane_setup(py, pz, c00, c01, c10, c11, wc);

    const uint4* base0 = (const uint4*)(g_tp16 + 0 * PLANE_ELEMS) + sub;
    const uint4* base1 = (const uint4*)(g_tp16 + 1 * PLANE_ELEMS) + sub;
    const uint4* base2 = (const uint4*)(g_tp16 + 2 * PLANE_ELEMS) + sub;

    // Issue all 12 loads before consuming any (MLP = 12).
    uint4 ra0 = __ldg(base0 + a00);
    uint4 ra1 = __ldg(base0 + a01);
    uint4 ra2 = __ldg(base0 + a10);
    uint4 ra3 = __ldg(base0 + a11);
    uint4 rb0 = __ldg(base1 + b00);
    uint4 rb1 = __ldg(base1 + b01);
    uint4 rb2 = __ldg(base1 + b10);
    uint4 rb3 = __ldg(base1 + b11);
    uint4 rc0 = __ldg(base2 + c00);
    uint4 rc1 = __ldg(base2 + c01);
    uint4 rc2 = __ldg(base2 + c10);
    uint4 rc3 = __ldg(base2 + c11);

    float acc[8];
    #pragma unroll
    for (int i = 0; i < 8; i++) acc[i] = 0.0f;

    plane_reduce(ra0, ra1, ra2, ra3, wa, acc);
    plane_reduce(rb0, rb1, rb2, rb3, wb, acc);
    plane_reduce(rc0, rc1, rc2, rc3, wc, acc);

    const float inv3 = 1.0f / 3.0f;
    float4 o0 = make_float4(acc[0] * inv3, acc[1] * inv3, acc[2] * inv3, acc[3] * inv3);
    float4 o1 = make_float4(acc[4] * inv3, acc[5] * inv3, acc[6] * inv3, acc[7] * inv3);
    float4* dst = (float4*)(out + p * FEAT) + sub * 2;
    dst[0] = o0;
    dst[1] = o1;
}

// ---------------------------------------------------------------------------
extern "C" void kernel_launch(void* const* d_in, const int* in_sizes, int n_in,
                              void* d_out, int out_size) {
    const float* x        = (const float*)d_in[0];
    const float* plane_xy = (const float*)d_in[1];
    const float* plane_xz = (const float*)d_in[2];
    const float* plane_yz = (const float*)d_in[3];
    float* out = (float*)d_out;

    dim3 tgrid(RES / 32, RES, 3);
    transpose_kernel<<<tgrid, 256>>>(plane_xy, plane_xz, plane_yz);

    const int threads = 256;
    const int blocks  = (NPTS * 8) / threads;
    sample_kernel<<<blocks, threads>>>(x, out);
}